// round 1
// baseline (speedup 1.0000x reference)
#include <cuda_runtime.h>
#include <cuda_bf16.h>
#include <cstdint>

#define BATCH   2
#define C_DIM   256
#define L_DIM   4096
#define N_GROUPS 32
#define CPG     8        // channels per group
#define NHEADS  4
#define HDIM    64
#define EPS_GN  1e-5f

// -------- scratch (device globals; no allocation allowed) --------
__device__ float g_xn [BATCH * C_DIM * L_DIM];        // 8 MB
__device__ float g_qkv[BATCH * 3 * C_DIM * L_DIM];    // 25 MB
__device__ float g_att[BATCH * C_DIM * L_DIM];        // 8 MB

// ============================================================
// GroupNorm: one CTA per (batch, group); group = 8 ch x 4096 = 32768 floats
// ============================================================
__global__ __launch_bounds__(256) void gn_kernel(const float* __restrict__ x,
                                                 const float* __restrict__ w,
                                                 const float* __restrict__ bias,
                                                 float* __restrict__ out)
{
    const int b = blockIdx.x >> 5;
    const int g = blockIdx.x & 31;
    const size_t base = ((size_t)b * C_DIM + (size_t)g * CPG) * L_DIM;
    const float4* xp = (const float4*)(x + base);
    float4*       op = (float4*)(out + base);
    const int tid = threadIdx.x;
    const int n4  = CPG * L_DIM / 4;   // 8192 float4

    float s = 0.f, sq = 0.f;
    #pragma unroll 4
    for (int i = tid; i < n4; i += 256) {
        float4 v = xp[i];
        s  += v.x + v.y + v.z + v.w;
        sq += v.x*v.x + v.y*v.y + v.z*v.z + v.w*v.w;
    }
    #pragma unroll
    for (int m = 16; m; m >>= 1) {
        s  += __shfl_xor_sync(0xffffffffu, s,  m);
        sq += __shfl_xor_sync(0xffffffffu, sq, m);
    }
    __shared__ float sa[8], sb[8], stats[2];
    if ((tid & 31) == 0) { sa[tid >> 5] = s; sb[tid >> 5] = sq; }
    __syncthreads();
    if (tid == 0) {
        float ts = 0.f, tq = 0.f;
        #pragma unroll
        for (int i = 0; i < 8; i++) { ts += sa[i]; tq += sb[i]; }
        const float inv_n = 1.f / (float)(CPG * L_DIM);
        float mean = ts * inv_n;
        float var  = tq * inv_n - mean * mean;   // biased, matches torch GroupNorm
        stats[0] = mean;
        stats[1] = rsqrtf(var + EPS_GN);
    }
    __syncthreads();
    const float mean = stats[0], rstd = stats[1];
    #pragma unroll 4
    for (int i = tid; i < n4; i += 256) {
        int cloc = i >> 10;                 // 1024 float4 per channel
        int c = g * CPG + cloc;
        float ww = w[c] * rstd;
        float bb = bias[c] - mean * ww;
        float4 v = xp[i];
        v.x = v.x * ww + bb;
        v.y = v.y * ww + bb;
        v.z = v.z * ww + bb;
        v.w = v.w * ww + bb;
        op[i] = v;
    }
}

// ============================================================
// SGEMM: C[b] = A[MxK] * Bm[b][KxN] + bias (+ resid).  64x64 tile, BK=16,
// 256 threads, 4x4 micro-tile per thread.
// ============================================================
__global__ __launch_bounds__(256) void gemm_kernel(const float* __restrict__ A,
                                                   const float* __restrict__ Bm,
                                                   const float* __restrict__ bias,
                                                   const float* __restrict__ resid,
                                                   float* __restrict__ Cm,
                                                   int M, int K, int N)
{
    __shared__ float As[16][64];
    __shared__ float Bs[16][64];
    const int bz = blockIdx.z;
    const float* Bp = Bm + (size_t)bz * K * N;
    float*       Cp = Cm + (size_t)bz * M * N;
    const int m0 = blockIdx.y * 64, n0 = blockIdx.x * 64;
    const int tid = threadIdx.x;
    const int tx = tid & 15, ty = tid >> 4;
    const int am = tid >> 2, ak = (tid & 3) * 4;      // A load: 64 rows x 16 k
    const int bk = tid >> 4, bn = (tid & 15) * 4;     // B load: 16 k x 64 n

    float acc[4][4] = {};
    for (int k0 = 0; k0 < K; k0 += 16) {
        float4 a = *(const float4*)(A + (size_t)(m0 + am) * K + k0 + ak);
        As[ak + 0][am] = a.x; As[ak + 1][am] = a.y;
        As[ak + 2][am] = a.z; As[ak + 3][am] = a.w;
        *(float4*)&Bs[bk][bn] =
            *(const float4*)(Bp + (size_t)(k0 + bk) * N + n0 + bn);
        __syncthreads();
        #pragma unroll
        for (int k = 0; k < 16; k++) {
            float4 av = *(const float4*)&As[k][ty * 4];
            float4 bv = *(const float4*)&Bs[k][tx * 4];
            acc[0][0] += av.x * bv.x; acc[0][1] += av.x * bv.y;
            acc[0][2] += av.x * bv.z; acc[0][3] += av.x * bv.w;
            acc[1][0] += av.y * bv.x; acc[1][1] += av.y * bv.y;
            acc[1][2] += av.y * bv.z; acc[1][3] += av.y * bv.w;
            acc[2][0] += av.z * bv.x; acc[2][1] += av.z * bv.y;
            acc[2][2] += av.z * bv.z; acc[2][3] += av.z * bv.w;
            acc[3][0] += av.w * bv.x; acc[3][1] += av.w * bv.y;
            acc[3][2] += av.w * bv.z; acc[3][3] += av.w * bv.w;
        }
        __syncthreads();
    }
    #pragma unroll
    for (int i = 0; i < 4; i++) {
        int m = m0 + ty * 4 + i;
        float bi = bias[m];
        float4 r = make_float4(acc[i][0] + bi, acc[i][1] + bi,
                               acc[i][2] + bi, acc[i][3] + bi);
        if (resid) {
            float4 rv = *(const float4*)(resid + (size_t)bz * M * N +
                                         (size_t)m * N + n0 + tx * 4);
            r.x += rv.x; r.y += rv.y; r.z += rv.z; r.w += rv.w;
        }
        *(float4*)(Cp + (size_t)m * N + n0 + tx * 4) = r;
    }
}

// ============================================================
// Flash attention, fp32.
//   Per (b,h): Q,K,V stored [d=64][L=4096] inside g_qkv.
//   out[m][n-logit] = softmax_n( (Q^T K)[m][n] / 8 ),  O[m][d] = P V^T
//   CTA: 64 query rows (m), loop over 64-wide key tiles.
//   256 threads = 16x16 grid; thread owns 4 rows x 4 cols.
// ============================================================
__global__ __launch_bounds__(256) void attn_kernel(const float* __restrict__ qkv,
                                                   float* __restrict__ att)
{
    extern __shared__ float smf[];
    float* Qs = smf;                 // [64][64]  (d, m), pre-scaled by 1/8
    float* Ks = smf + 4096;          // [64][64]  (d, n)
    float* Vs = smf + 8192;          // [64][64]  (n, d)
    float* Ps = smf + 12288;         // [64][68]  P[m][n]; reused as Ot[d][m]

    const int bh = blockIdx.y;               // 0..7
    const int b = bh >> 2, h = bh & 3;
    const int m0 = blockIdx.x * 64;
    const float* Qg = qkv + ((size_t)b * 3 * C_DIM + (size_t)h * HDIM) * L_DIM;
    const float* Kg = Qg + (size_t)C_DIM * L_DIM;
    const float* Vg = Qg + (size_t)2 * C_DIM * L_DIM;

    const int tid = threadIdx.x;
    const int tx = tid & 15, ty = tid >> 4;
    const int ld = tid >> 2;              // load row (d), 0..63
    const int lc = (tid & 3) * 16;        // load col base

    // ---- load Q tile (scaled) ----
    #pragma unroll
    for (int k = 0; k < 4; k++) {
        float4 v = *(const float4*)(Qg + (size_t)ld * L_DIM + m0 + lc + k * 4);
        v.x *= 0.125f; v.y *= 0.125f; v.z *= 0.125f; v.w *= 0.125f;
        *(float4*)&Qs[ld * 64 + lc + k * 4] = v;
    }

    float o[4][4] = {};
    float mprev[4] = {-1e30f, -1e30f, -1e30f, -1e30f};
    float lsum[4] = {};

    for (int n0 = 0; n0 < L_DIM; n0 += 64) {
        __syncthreads();   // prev iteration's reads of Ks/Vs/Ps are done
        #pragma unroll
        for (int k = 0; k < 4; k++) {
            float4 kv = *(const float4*)(Kg + (size_t)ld * L_DIM + n0 + lc + k * 4);
            *(float4*)&Ks[ld * 64 + lc + k * 4] = kv;
            float4 vv = *(const float4*)(Vg + (size_t)ld * L_DIM + n0 + lc + k * 4);
            const int nb = lc + k * 4;
            Vs[(nb + 0) * 64 + ld] = vv.x;
            Vs[(nb + 1) * 64 + ld] = vv.y;
            Vs[(nb + 2) * 64 + ld] = vv.z;
            Vs[(nb + 3) * 64 + ld] = vv.w;
        }
        __syncthreads();

        // ---- S = Q^T K (64x64x64) ----
        float s[4][4] = {};
        #pragma unroll
        for (int kd = 0; kd < 64; kd++) {
            float4 qa = *(const float4*)&Qs[kd * 64 + ty * 4];
            float4 kb = *(const float4*)&Ks[kd * 64 + tx * 4];
            s[0][0] += qa.x * kb.x; s[0][1] += qa.x * kb.y;
            s[0][2] += qa.x * kb.z; s[0][3] += qa.x * kb.w;
            s[1][0] += qa.y * kb.x; s[1][1] += qa.y * kb.y;
            s[1][2] += qa.y * kb.z; s[1][3] += qa.y * kb.w;
            s[2][0] += qa.z * kb.x; s[2][1] += qa.z * kb.y;
            s[2][2] += qa.z * kb.z; s[2][3] += qa.z * kb.w;
            s[3][0] += qa.w * kb.x; s[3][1] += qa.w * kb.y;
            s[3][2] += qa.w * kb.z; s[3][3] += qa.w * kb.w;
        }

        // ---- online softmax (row reduce across the 16 tx lanes) ----
        #pragma unroll
        for (int i = 0; i < 4; i++) {
            float mx = fmaxf(fmaxf(s[i][0], s[i][1]), fmaxf(s[i][2], s[i][3]));
            mx = fmaxf(mx, __shfl_xor_sync(0xffffffffu, mx, 1));
            mx = fmaxf(mx, __shfl_xor_sync(0xffffffffu, mx, 2));
            mx = fmaxf(mx, __shfl_xor_sync(0xffffffffu, mx, 4));
            mx = fmaxf(mx, __shfl_xor_sync(0xffffffffu, mx, 8));
            float mnew = fmaxf(mprev[i], mx);
            float alpha = __expf(mprev[i] - mnew);
            mprev[i] = mnew;
            float r = 0.f;
            #pragma unroll
            for (int j = 0; j < 4; j++) {
                s[i][j] = __expf(s[i][j] - mnew);
                r += s[i][j];
            }
            r += __shfl_xor_sync(0xffffffffu, r, 1);
            r += __shfl_xor_sync(0xffffffffu, r, 2);
            r += __shfl_xor_sync(0xffffffffu, r, 4);
            r += __shfl_xor_sync(0xffffffffu, r, 8);
            lsum[i] = lsum[i] * alpha + r;
            #pragma unroll
            for (int j = 0; j < 4; j++) o[i][j] *= alpha;
            *(float4*)&Ps[(ty * 4 + i) * 68 + tx * 4] =
                make_float4(s[i][0], s[i][1], s[i][2], s[i][3]);
        }
        __syncthreads();

        // ---- O += P * V (64x64x64) ----
        #pragma unroll
        for (int kn = 0; kn < 64; kn++) {
            float4 vv = *(const float4*)&Vs[kn * 64 + tx * 4];
            float p0 = Ps[(ty * 4 + 0) * 68 + kn];
            float p1 = Ps[(ty * 4 + 1) * 68 + kn];
            float p2 = Ps[(ty * 4 + 2) * 68 + kn];
            float p3 = Ps[(ty * 4 + 3) * 68 + kn];
            o[0][0] += p0 * vv.x; o[0][1] += p0 * vv.y;
            o[0][2] += p0 * vv.z; o[0][3] += p0 * vv.w;
            o[1][0] += p1 * vv.x; o[1][1] += p1 * vv.y;
            o[1][2] += p1 * vv.z; o[1][3] += p1 * vv.w;
            o[2][0] += p2 * vv.x; o[2][1] += p2 * vv.y;
            o[2][2] += p2 * vv.z; o[2][3] += p2 * vv.w;
            o[3][0] += p3 * vv.x; o[3][1] += p3 * vv.y;
            o[3][2] += p3 * vv.z; o[3][3] += p3 * vv.w;
        }
    }
    __syncthreads();   // last PV reads of Ps done before reuse

    // ---- normalize, transpose via smem, coalesced store as att[d][m] ----
    #pragma unroll
    for (int i = 0; i < 4; i++) {
        float inv = 1.f / lsum[i];
        #pragma unroll
        for (int j = 0; j < 4; j++)
            Ps[(tx * 4 + j) * 68 + ty * 4 + i] = o[i][j] * inv;  // Ot[d][m]
    }
    __syncthreads();
    #pragma unroll
    for (int k = 0; k < 4; k++) {
        float4 r = *(const float4*)&Ps[ld * 68 + lc + k * 4];
        *(float4*)(att + ((size_t)b * C_DIM + (size_t)h * HDIM + ld) * L_DIM +
                   m0 + lc + k * 4) = r;
    }
}

// ============================================================
// launch
// ============================================================
extern "C" void kernel_launch(void* const* d_in, const int* in_sizes, int n_in,
                              void* d_out, int out_size)
{
    const float* x    = (const float*)d_in[0];
    const float* gnw  = (const float*)d_in[1];
    const float* gnb  = (const float*)d_in[2];
    const float* qkvw = (const float*)d_in[3];
    const float* qkvb = (const float*)d_in[4];
    const float* pw   = (const float*)d_in[5];
    const float* pb   = (const float*)d_in[6];
    float* out = (float*)d_out;

    void* p;
    cudaGetSymbolAddress(&p, g_xn);  float* xn  = (float*)p;
    cudaGetSymbolAddress(&p, g_qkv); float* qkv = (float*)p;
    cudaGetSymbolAddress(&p, g_att); float* att = (float*)p;

    gn_kernel<<<BATCH * N_GROUPS, 256>>>(x, gnw, gnb, xn);

    gemm_kernel<<<dim3(L_DIM / 64, (3 * C_DIM) / 64, BATCH), 256>>>(
        qkvw, xn, qkvb, nullptr, qkv, 3 * C_DIM, C_DIM, L_DIM);

    const int smem_bytes = (4096 * 3 + 64 * 68) * (int)sizeof(float);  // 66560
    cudaFuncSetAttribute(attn_kernel,
                         cudaFuncAttributeMaxDynamicSharedMemorySize, smem_bytes);
    attn_kernel<<<dim3(L_DIM / 64, BATCH * NHEADS), 256, smem_bytes>>>(qkv, att);

    gemm_kernel<<<dim3(L_DIM / 64, C_DIM / 64, BATCH), 256>>>(
        pw, att, pb, x, out, C_DIM, C_DIM, L_DIM);
}

// round 2
// speedup vs baseline: 1.0017x; 1.0017x over previous
#include <cuda_runtime.h>
#include <cuda_bf16.h>
#include <cstdint>

#define BATCH   2
#define C_DIM   256
#define L_DIM   4096
#define N_GROUPS 32
#define CPG     8        // channels per group
#define NHEADS  4
#define HDIM    64
#define EPS_GN  1e-5f

// -------- scratch (device globals; no allocation allowed) --------
__device__ float g_xn [BATCH * C_DIM * L_DIM];        // 8 MB
__device__ float g_qkv[BATCH * 3 * C_DIM * L_DIM];    // 25 MB
__device__ float g_att[BATCH * C_DIM * L_DIM];        // 8 MB

// ============================================================
// GroupNorm: one CTA per (batch, group); group = 8 ch x 4096 = 32768 floats
// ============================================================
__global__ __launch_bounds__(256) void gn_kernel(const float* __restrict__ x,
                                                 const float* __restrict__ w,
                                                 const float* __restrict__ bias,
                                                 float* __restrict__ out)
{
    const int b = blockIdx.x >> 5;
    const int g = blockIdx.x & 31;
    const size_t base = ((size_t)b * C_DIM + (size_t)g * CPG) * L_DIM;
    const float4* xp = (const float4*)(x + base);
    float4*       op = (float4*)(out + base);
    const int tid = threadIdx.x;
    const int n4  = CPG * L_DIM / 4;   // 8192 float4

    float s = 0.f, sq = 0.f;
    #pragma unroll 4
    for (int i = tid; i < n4; i += 256) {
        float4 v = xp[i];
        s  += v.x + v.y + v.z + v.w;
        sq += v.x*v.x + v.y*v.y + v.z*v.z + v.w*v.w;
    }
    #pragma unroll
    for (int m = 16; m; m >>= 1) {
        s  += __shfl_xor_sync(0xffffffffu, s,  m);
        sq += __shfl_xor_sync(0xffffffffu, sq, m);
    }
    __shared__ float sa[8], sb[8], stats[2];
    if ((tid & 31) == 0) { sa[tid >> 5] = s; sb[tid >> 5] = sq; }
    __syncthreads();
    if (tid == 0) {
        float ts = 0.f, tq = 0.f;
        #pragma unroll
        for (int i = 0; i < 8; i++) { ts += sa[i]; tq += sb[i]; }
        const float inv_n = 1.f / (float)(CPG * L_DIM);
        float mean = ts * inv_n;
        float var  = tq * inv_n - mean * mean;   // biased, matches torch GroupNorm
        stats[0] = mean;
        stats[1] = rsqrtf(var + EPS_GN);
    }
    __syncthreads();
    const float mean = stats[0], rstd = stats[1];
    #pragma unroll 4
    for (int i = tid; i < n4; i += 256) {
        int cloc = i >> 10;                 // 1024 float4 per channel
        int c = g * CPG + cloc;
        float ww = w[c] * rstd;
        float bb = bias[c] - mean * ww;
        float4 v = xp[i];
        v.x = v.x * ww + bb;
        v.y = v.y * ww + bb;
        v.z = v.z * ww + bb;
        v.w = v.w * ww + bb;
        op[i] = v;
    }
}

// ============================================================
// SGEMM: C[b] = A[MxK] * Bm[b][KxN] + bias (+ resid).  64x64 tile, BK=16,
// 256 threads, 4x4 micro-tile per thread.
// ============================================================
__global__ __launch_bounds__(256) void gemm_kernel(const float* __restrict__ A,
                                                   const float* __restrict__ Bm,
                                                   const float* __restrict__ bias,
                                                   const float* __restrict__ resid,
                                                   float* __restrict__ Cm,
                                                   int M, int K, int N)
{
    __shared__ float As[16][64];
    __shared__ float Bs[16][64];
    const int bz = blockIdx.z;
    const float* Bp = Bm + (size_t)bz * K * N;
    float*       Cp = Cm + (size_t)bz * M * N;
    const int m0 = blockIdx.y * 64, n0 = blockIdx.x * 64;
    const int tid = threadIdx.x;
    const int tx = tid & 15, ty = tid >> 4;
    const int am = tid >> 2, ak = (tid & 3) * 4;      // A load: 64 rows x 16 k
    const int bk = tid >> 4, bn = (tid & 15) * 4;     // B load: 16 k x 64 n

    float acc[4][4] = {};
    for (int k0 = 0; k0 < K; k0 += 16) {
        float4 a = *(const float4*)(A + (size_t)(m0 + am) * K + k0 + ak);
        As[ak + 0][am] = a.x; As[ak + 1][am] = a.y;
        As[ak + 2][am] = a.z; As[ak + 3][am] = a.w;
        *(float4*)&Bs[bk][bn] =
            *(const float4*)(Bp + (size_t)(k0 + bk) * N + n0 + bn);
        __syncthreads();
        #pragma unroll
        for (int k = 0; k < 16; k++) {
            float4 av = *(const float4*)&As[k][ty * 4];
            float4 bv = *(const float4*)&Bs[k][tx * 4];
            acc[0][0] += av.x * bv.x; acc[0][1] += av.x * bv.y;
            acc[0][2] += av.x * bv.z; acc[0][3] += av.x * bv.w;
            acc[1][0] += av.y * bv.x; acc[1][1] += av.y * bv.y;
            acc[1][2] += av.y * bv.z; acc[1][3] += av.y * bv.w;
            acc[2][0] += av.z * bv.x; acc[2][1] += av.z * bv.y;
            acc[2][2] += av.z * bv.z; acc[2][3] += av.z * bv.w;
            acc[3][0] += av.w * bv.x; acc[3][1] += av.w * bv.y;
            acc[3][2] += av.w * bv.z; acc[3][3] += av.w * bv.w;
        }
        __syncthreads();
    }
    #pragma unroll
    for (int i = 0; i < 4; i++) {
        int m = m0 + ty * 4 + i;
        float bi = bias[m];
        float4 r = make_float4(acc[i][0] + bi, acc[i][1] + bi,
                               acc[i][2] + bi, acc[i][3] + bi);
        if (resid) {
            float4 rv = *(const float4*)(resid + (size_t)bz * M * N +
                                         (size_t)m * N + n0 + tx * 4);
            r.x += rv.x; r.y += rv.y; r.z += rv.z; r.w += rv.w;
        }
        *(float4*)(Cp + (size_t)m * N + n0 + tx * 4) = r;
    }
}

// ============================================================
// Flash attention, fp32.
//   Per (b,h): Q,K,V stored [d=64][L=4096] inside g_qkv.
//   out[m][n-logit] = softmax_n( (Q^T K)[m][n] / 8 ),  O[m][d] = P V^T
//   CTA: 64 query rows (m), loop over 64-wide key tiles.
//   256 threads = 16x16 grid; thread owns 4 rows x 4 cols.
// ============================================================
__global__ __launch_bounds__(256) void attn_kernel(const float* __restrict__ qkv,
                                                   float* __restrict__ att)
{
    extern __shared__ float smf[];
    float* Qs = smf;                 // [64][64]  (d, m), pre-scaled by 1/8
    float* Ks = smf + 4096;          // [64][64]  (d, n)
    float* Vs = smf + 8192;          // [64][64]  (n, d)
    float* Ps = smf + 12288;         // [64][68]  P[m][n]; reused as Ot[d][m]

    const int bh = blockIdx.y;               // 0..7
    const int b = bh >> 2, h = bh & 3;
    const int m0 = blockIdx.x * 64;
    const float* Qg = qkv + ((size_t)b * 3 * C_DIM + (size_t)h * HDIM) * L_DIM;
    const float* Kg = Qg + (size_t)C_DIM * L_DIM;
    const float* Vg = Qg + (size_t)2 * C_DIM * L_DIM;

    const int tid = threadIdx.x;
    const int tx = tid & 15, ty = tid >> 4;
    const int ld = tid >> 2;              // load row (d), 0..63
    const int lc = (tid & 3) * 16;        // load col base

    // ---- load Q tile (scaled) ----
    #pragma unroll
    for (int k = 0; k < 4; k++) {
        float4 v = *(const float4*)(Qg + (size_t)ld * L_DIM + m0 + lc + k * 4);
        v.x *= 0.125f; v.y *= 0.125f; v.z *= 0.125f; v.w *= 0.125f;
        *(float4*)&Qs[ld * 64 + lc + k * 4] = v;
    }

    float o[4][4] = {};
    float mprev[4] = {-1e30f, -1e30f, -1e30f, -1e30f};
    float lsum[4] = {};

    for (int n0 = 0; n0 < L_DIM; n0 += 64) {
        __syncthreads();   // prev iteration's reads of Ks/Vs/Ps are done
        #pragma unroll
        for (int k = 0; k < 4; k++) {
            float4 kv = *(const float4*)(Kg + (size_t)ld * L_DIM + n0 + lc + k * 4);
            *(float4*)&Ks[ld * 64 + lc + k * 4] = kv;
            float4 vv = *(const float4*)(Vg + (size_t)ld * L_DIM + n0 + lc + k * 4);
            const int nb = lc + k * 4;
            Vs[(nb + 0) * 64 + ld] = vv.x;
            Vs[(nb + 1) * 64 + ld] = vv.y;
            Vs[(nb + 2) * 64 + ld] = vv.z;
            Vs[(nb + 3) * 64 + ld] = vv.w;
        }
        __syncthreads();

        // ---- S = Q^T K (64x64x64) ----
        float s[4][4] = {};
        #pragma unroll
        for (int kd = 0; kd < 64; kd++) {
            float4 qa = *(const float4*)&Qs[kd * 64 + ty * 4];
            float4 kb = *(const float4*)&Ks[kd * 64 + tx * 4];
            s[0][0] += qa.x * kb.x; s[0][1] += qa.x * kb.y;
            s[0][2] += qa.x * kb.z; s[0][3] += qa.x * kb.w;
            s[1][0] += qa.y * kb.x; s[1][1] += qa.y * kb.y;
            s[1][2] += qa.y * kb.z; s[1][3] += qa.y * kb.w;
            s[2][0] += qa.z * kb.x; s[2][1] += qa.z * kb.y;
            s[2][2] += qa.z * kb.z; s[2][3] += qa.z * kb.w;
            s[3][0] += qa.w * kb.x; s[3][1] += qa.w * kb.y;
            s[3][2] += qa.w * kb.z; s[3][3] += qa.w * kb.w;
        }

        // ---- online softmax (row reduce across the 16 tx lanes) ----
        #pragma unroll
        for (int i = 0; i < 4; i++) {
            float mx = fmaxf(fmaxf(s[i][0], s[i][1]), fmaxf(s[i][2], s[i][3]));
            mx = fmaxf(mx, __shfl_xor_sync(0xffffffffu, mx, 1));
            mx = fmaxf(mx, __shfl_xor_sync(0xffffffffu, mx, 2));
            mx = fmaxf(mx, __shfl_xor_sync(0xffffffffu, mx, 4));
            mx = fmaxf(mx, __shfl_xor_sync(0xffffffffu, mx, 8));
            float mnew = fmaxf(mprev[i], mx);
            float alpha = __expf(mprev[i] - mnew);
            mprev[i] = mnew;
            float r = 0.f;
            #pragma unroll
            for (int j = 0; j < 4; j++) {
                s[i][j] = __expf(s[i][j] - mnew);
                r += s[i][j];
            }
            r += __shfl_xor_sync(0xffffffffu, r, 1);
            r += __shfl_xor_sync(0xffffffffu, r, 2);
            r += __shfl_xor_sync(0xffffffffu, r, 4);
            r += __shfl_xor_sync(0xffffffffu, r, 8);
            lsum[i] = lsum[i] * alpha + r;
            #pragma unroll
            for (int j = 0; j < 4; j++) o[i][j] *= alpha;
            *(float4*)&Ps[(ty * 4 + i) * 68 + tx * 4] =
                make_float4(s[i][0], s[i][1], s[i][2], s[i][3]);
        }
        __syncthreads();

        // ---- O += P * V (64x64x64) ----
        #pragma unroll
        for (int kn = 0; kn < 64; kn++) {
            float4 vv = *(const float4*)&Vs[kn * 64 + tx * 4];
            float p0 = Ps[(ty * 4 + 0) * 68 + kn];
            float p1 = Ps[(ty * 4 + 1) * 68 + kn];
            float p2 = Ps[(ty * 4 + 2) * 68 + kn];
            float p3 = Ps[(ty * 4 + 3) * 68 + kn];
            o[0][0] += p0 * vv.x; o[0][1] += p0 * vv.y;
            o[0][2] += p0 * vv.z; o[0][3] += p0 * vv.w;
            o[1][0] += p1 * vv.x; o[1][1] += p1 * vv.y;
            o[1][2] += p1 * vv.z; o[1][3] += p1 * vv.w;
            o[2][0] += p2 * vv.x; o[2][1] += p2 * vv.y;
            o[2][2] += p2 * vv.z; o[2][3] += p2 * vv.w;
            o[3][0] += p3 * vv.x; o[3][1] += p3 * vv.y;
            o[3][2] += p3 * vv.z; o[3][3] += p3 * vv.w;
        }
    }
    __syncthreads();   // last PV reads of Ps done before reuse

    // ---- normalize, transpose via smem, coalesced store as att[d][m] ----
    #pragma unroll
    for (int i = 0; i < 4; i++) {
        float inv = 1.f / lsum[i];
        #pragma unroll
        for (int j = 0; j < 4; j++)
            Ps[(tx * 4 + j) * 68 + ty * 4 + i] = o[i][j] * inv;  // Ot[d][m]
    }
    __syncthreads();
    #pragma unroll
    for (int k = 0; k < 4; k++) {
        float4 r = *(const float4*)&Ps[ld * 68 + lc + k * 4];
        *(float4*)(att + ((size_t)b * C_DIM + (size_t)h * HDIM + ld) * L_DIM +
                   m0 + lc + k * 4) = r;
    }
}

// ============================================================
// launch
// ============================================================
extern "C" void kernel_launch(void* const* d_in, const int* in_sizes, int n_in,
                              void* d_out, int out_size)
{
    const float* x    = (const float*)d_in[0];
    const float* gnw  = (const float*)d_in[1];
    const float* gnb  = (const float*)d_in[2];
    const float* qkvw = (const float*)d_in[3];
    const float* qkvb = (const float*)d_in[4];
    const float* pw   = (const float*)d_in[5];
    const float* pb   = (const float*)d_in[6];
    float* out = (float*)d_out;

    void* p;
    cudaGetSymbolAddress(&p, g_xn);  float* xn  = (float*)p;
    cudaGetSymbolAddress(&p, g_qkv); float* qkv = (float*)p;
    cudaGetSymbolAddress(&p, g_att); float* att = (float*)p;

    gn_kernel<<<BATCH * N_GROUPS, 256>>>(x, gnw, gnb, xn);

    gemm_kernel<<<dim3(L_DIM / 64, (3 * C_DIM) / 64, BATCH), 256>>>(
        qkvw, xn, qkvb, nullptr, qkv, 3 * C_DIM, C_DIM, L_DIM);

    const int smem_bytes = (4096 * 3 + 64 * 68) * (int)sizeof(float);  // 66560
    cudaFuncSetAttribute(attn_kernel,
                         cudaFuncAttributeMaxDynamicSharedMemorySize, smem_bytes);
    attn_kernel<<<dim3(L_DIM / 64, BATCH * NHEADS), 256, smem_bytes>>>(qkv, att);

    gemm_kernel<<<dim3(L_DIM / 64, C_DIM / 64, BATCH), 256>>>(
        pw, att, pb, x, out, C_DIM, C_DIM, L_DIM);
}

// round 4
// speedup vs baseline: 1.9477x; 1.9444x over previous
#include <cuda_runtime.h>
#include <cuda_bf16.h>
#include <cstdint>

#define BATCH   2
#define C_DIM   256
#define L_DIM   4096
#define N_GROUPS 32
#define CPG     8
#define NHEADS  4
#define HDIM    64
#define EPS_GN  1e-5f

__device__ float g_xn [BATCH * C_DIM * L_DIM];
__device__ float g_qkv[BATCH * 3 * C_DIM * L_DIM];
__device__ float g_att[BATCH * C_DIM * L_DIM];

// ============================================================
// GroupNorm (unchanged)
// ============================================================
__global__ __launch_bounds__(256) void gn_kernel(const float* __restrict__ x,
                                                 const float* __restrict__ w,
                                                 const float* __restrict__ bias,
                                                 float* __restrict__ out)
{
    const int b = blockIdx.x >> 5;
    const int g = blockIdx.x & 31;
    const size_t base = ((size_t)b * C_DIM + (size_t)g * CPG) * L_DIM;
    const float4* xp = (const float4*)(x + base);
    float4*       op = (float4*)(out + base);
    const int tid = threadIdx.x;
    const int n4  = CPG * L_DIM / 4;

    float s = 0.f, sq = 0.f;
    #pragma unroll 4
    for (int i = tid; i < n4; i += 256) {
        float4 v = xp[i];
        s  += v.x + v.y + v.z + v.w;
        sq += v.x*v.x + v.y*v.y + v.z*v.z + v.w*v.w;
    }
    #pragma unroll
    for (int m = 16; m; m >>= 1) {
        s  += __shfl_xor_sync(0xffffffffu, s,  m);
        sq += __shfl_xor_sync(0xffffffffu, sq, m);
    }
    __shared__ float sa[8], sb[8], stats[2];
    if ((tid & 31) == 0) { sa[tid >> 5] = s; sb[tid >> 5] = sq; }
    __syncthreads();
    if (tid == 0) {
        float ts = 0.f, tq = 0.f;
        #pragma unroll
        for (int i = 0; i < 8; i++) { ts += sa[i]; tq += sb[i]; }
        const float inv_n = 1.f / (float)(CPG * L_DIM);
        float mean = ts * inv_n;
        float var  = tq * inv_n - mean * mean;
        stats[0] = mean;
        stats[1] = rsqrtf(var + EPS_GN);
    }
    __syncthreads();
    const float mean = stats[0], rstd = stats[1];
    #pragma unroll 4
    for (int i = tid; i < n4; i += 256) {
        int cloc = i >> 10;
        int c = g * CPG + cloc;
        float ww = w[c] * rstd;
        float bb = bias[c] - mean * ww;
        float4 v = xp[i];
        v.x = v.x * ww + bb; v.y = v.y * ww + bb;
        v.z = v.z * ww + bb; v.w = v.w * ww + bb;
        op[i] = v;
    }
}

// ============================================================
// SGEMM (unchanged)
// ============================================================
__global__ __launch_bounds__(256) void gemm_kernel(const float* __restrict__ A,
                                                   const float* __restrict__ Bm,
                                                   const float* __restrict__ bias,
                                                   const float* __restrict__ resid,
                                                   float* __restrict__ Cm,
                                                   int M, int K, int N)
{
    __shared__ float As[16][64];
    __shared__ float Bs[16][64];
    const int bz = blockIdx.z;
    const float* Bp = Bm + (size_t)bz * K * N;
    float*       Cp = Cm + (size_t)bz * M * N;
    const int m0 = blockIdx.y * 64, n0 = blockIdx.x * 64;
    const int tid = threadIdx.x;
    const int tx = tid & 15, ty = tid >> 4;
    const int am = tid >> 2, ak = (tid & 3) * 4;
    const int bk = tid >> 4, bn = (tid & 15) * 4;

    float acc[4][4] = {};
    for (int k0 = 0; k0 < K; k0 += 16) {
        float4 a = *(const float4*)(A + (size_t)(m0 + am) * K + k0 + ak);
        As[ak + 0][am] = a.x; As[ak + 1][am] = a.y;
        As[ak + 2][am] = a.z; As[ak + 3][am] = a.w;
        *(float4*)&Bs[bk][bn] =
            *(const float4*)(Bp + (size_t)(k0 + bk) * N + n0 + bn);
        __syncthreads();
        #pragma unroll
        for (int k = 0; k < 16; k++) {
            float4 av = *(const float4*)&As[k][ty * 4];
            float4 bv = *(const float4*)&Bs[k][tx * 4];
            acc[0][0] += av.x * bv.x; acc[0][1] += av.x * bv.y;
            acc[0][2] += av.x * bv.z; acc[0][3] += av.x * bv.w;
            acc[1][0] += av.y * bv.x; acc[1][1] += av.y * bv.y;
            acc[1][2] += av.y * bv.z; acc[1][3] += av.y * bv.w;
            acc[2][0] += av.z * bv.x; acc[2][1] += av.z * bv.y;
            acc[2][2] += av.z * bv.z; acc[2][3] += av.z * bv.w;
            acc[3][0] += av.w * bv.x; acc[3][1] += av.w * bv.y;
            acc[3][2] += av.w * bv.z; acc[3][3] += av.w * bv.w;
        }
        __syncthreads();
    }
    #pragma unroll
    for (int i = 0; i < 4; i++) {
        int m = m0 + ty * 4 + i;
        float bi = bias[m];
        float4 r = make_float4(acc[i][0] + bi, acc[i][1] + bi,
                               acc[i][2] + bi, acc[i][3] + bi);
        if (resid) {
            float4 rv = *(const float4*)(resid + (size_t)bz * M * N +
                                         (size_t)m * N + n0 + tx * 4);
            r.x += rv.x; r.y += rv.y; r.z += rv.z; r.w += rv.w;
        }
        *(float4*)(Cp + (size_t)m * N + n0 + tx * 4) = r;
    }
}

// ============================================================
// helpers for mma.sync attention
// ============================================================
__device__ __forceinline__ uint32_t smem_u32(const void* p) {
    uint32_t a;
    asm("{ .reg .u64 t; cvta.to.shared.u64 t, %1; cvt.u32.u64 %0, t; }"
        : "=r"(a) : "l"(p));
    return a;
}

__device__ __forceinline__ void mma_bf16(float* d, const uint32_t* a,
                                         uint32_t b0, uint32_t b1) {
    asm volatile(
        "mma.sync.aligned.m16n8k16.row.col.f32.bf16.bf16.f32 "
        "{%0,%1,%2,%3}, {%4,%5,%6,%7}, {%8,%9}, {%0,%1,%2,%3};\n"
        : "+f"(d[0]), "+f"(d[1]), "+f"(d[2]), "+f"(d[3])
        : "r"(a[0]), "r"(a[1]), "r"(a[2]), "r"(a[3]), "r"(b0), "r"(b1));
}

#define CPA(dst, src) \
    asm volatile("cp.async.cg.shared.global [%0], [%1], 16;" \
                 :: "r"(dst), "l"(src) : "memory")
#define CP_COMMIT() asm volatile("cp.async.commit_group;" ::: "memory")
#define CP_WAIT0()  asm volatile("cp.async.wait_group 0;" ::: "memory")

#define SWZ(o) ((o) ^ (((o) >> 3) & 0x70))

// smem byte offsets (dynamic smem, 64KB)
#define OFF_STG 0         // 32KB raw fp32 stage (K @0, V @16384; Q prologue 32KB)
#define OFF_KH  32768     // K^T [key][d] bf16 hi, 8KB, SW128
#define OFF_KL  40960
#define OFF_VH  49152     // V [d][key] bf16 hi, 8KB, SW128
#define OFF_VL  57344
#define SMEM_ATTN 65536
#define OPITCH  132       // O staging pitch (floats), reuses smem offset 0

// exp on the FMA pipe (no MUFU): exp2 magic-round + deg-5 poly
__device__ __forceinline__ float fastexp(float x) {
    x = fminf(fmaxf(x, -60.f), 60.f);
    float y = x * 1.4426950408889634f;
    float t = y + 12582912.f;
    int   n = __float_as_int(t) - 0x4B400000;
    float f = y - (t - 12582912.f);
    float p =           1.3333558146e-3f;
    p = fmaf(p, f, 9.6181291076e-3f);
    p = fmaf(p, f, 5.5504108665e-2f);
    p = fmaf(p, f, 2.4022650696e-1f);
    p = fmaf(p, f, 6.9314718056e-1f);
    p = fmaf(p, f, 1.0f);
    return p * __int_as_float((n + 127) << 23);
}

__device__ __forceinline__ uint32_t pack2(__nv_bfloat16 a, __nv_bfloat16 b) {
    __nv_bfloat162 t = __halves2bfloat162(a, b);   // low = a, high = b
    return *reinterpret_cast<uint32_t*>(&t);
}
__device__ __forceinline__ void bsplit(float v, __nv_bfloat16& h, __nv_bfloat16& l) {
    h = __float2bfloat16_rn(v);
    l = __float2bfloat16_rn(v - __bfloat162float(h));
}

// issue cp.async for K,V tile (raw fp32 [64 d][64 key] each)
__device__ __forceinline__ void stage_kv(uint32_t sb, const float* __restrict__ Kg,
                                         const float* __restrict__ Vg,
                                         int n0, int tid) {
    #pragma unroll
    for (int it = 0; it < 4; it++) {
        int i = tid + it * 256;            // 0..1023
        int d = i >> 4, k4 = (i & 15) << 2;
        CPA(sb + OFF_STG + (uint32_t)(d * 64 + k4) * 4,
            Kg + (size_t)d * L_DIM + n0 + k4);
        CPA(sb + OFF_STG + 16384u + (uint32_t)(d * 64 + k4) * 4,
            Vg + (size_t)d * L_DIM + n0 + k4);
    }
    CP_COMMIT();
}

// convert staged raw fp32 -> bf16 hi/lo tiles (K transposed to [key][d])
__device__ __forceinline__ void convert_kv(char* sm, int tid) {
    const float* Kst = (const float*)(sm + OFF_STG);
    const float* Vst = (const float*)(sm + OFF_STG + 16384);
    #pragma unroll
    for (int it = 0; it < 4; it++) {
        int i = tid + it * 256;
        int d = i >> 4, k4 = (i & 15) << 2;
        float4 kv = *(const float4*)(Kst + d * 64 + k4);
        __nv_bfloat16 h, l;
        bsplit(kv.x, h, l);
        { uint32_t o = SWZ((uint32_t)(k4+0)*128 + d*2);
          *(__nv_bfloat16*)(sm+OFF_KH+o) = h; *(__nv_bfloat16*)(sm+OFF_KL+o) = l; }
        bsplit(kv.y, h, l);
        { uint32_t o = SWZ((uint32_t)(k4+1)*128 + d*2);
          *(__nv_bfloat16*)(sm+OFF_KH+o) = h; *(__nv_bfloat16*)(sm+OFF_KL+o) = l; }
        bsplit(kv.z, h, l);
        { uint32_t o = SWZ((uint32_t)(k4+2)*128 + d*2);
          *(__nv_bfloat16*)(sm+OFF_KH+o) = h; *(__nv_bfloat16*)(sm+OFF_KL+o) = l; }
        bsplit(kv.w, h, l);
        { uint32_t o = SWZ((uint32_t)(k4+3)*128 + d*2);
          *(__nv_bfloat16*)(sm+OFF_KH+o) = h; *(__nv_bfloat16*)(sm+OFF_KL+o) = l; }

        float4 vv = *(const float4*)(Vst + d * 64 + k4);
        __nv_bfloat16 h0,l0,h1,l1,h2,l2,h3,l3;
        bsplit(vv.x, h0, l0); bsplit(vv.y, h1, l1);
        bsplit(vv.z, h2, l2); bsplit(vv.w, h3, l3);
        uint32_t o = SWZ((uint32_t)d*128 + k4*2);
        *(uint2*)(sm + OFF_VH + o) = make_uint2(pack2(h0,h1), pack2(h2,h3));
        *(uint2*)(sm + OFF_VL + o) = make_uint2(pack2(l0,l1), pack2(l2,l3));
    }
}

// ============================================================
// mma.sync bf16 split-precision flash attention
// CTA: 128 queries x (b,h); 8 warps, each owns 16 query rows.
// ============================================================
__global__ __launch_bounds__(256) void attn_mma(const float* __restrict__ qkv,
                                                float* __restrict__ att)
{
    extern __shared__ char sm[];
    const uint32_t sb = smem_u32(sm);
    const int tid = threadIdx.x;
    const int w = tid >> 5, l = tid & 31;
    const int lg = l >> 2;                 // group 0..7
    const int c2 = (l & 3) * 2;            // even col within tile
    const int r0 = w * 16 + lg;            // query row (within 128-tile)
    const int r1 = r0 + 8;

    const int bh = blockIdx.y, b = bh >> 2, h = bh & 3;
    const int q0 = blockIdx.x << 7;
    const float* Qg = qkv + ((size_t)b * 3 * C_DIM + (size_t)h * HDIM) * L_DIM;
    const float* Kg = Qg + (size_t)C_DIM * L_DIM;
    const float* Vg = Qg + (size_t)2 * C_DIM * L_DIM;

    // ---- prologue: stage Q raw [64 d][128 q], build A fragments ----
    #pragma unroll
    for (int it = 0; it < 8; it++) {
        int i = tid + it * 256;            // 0..2047
        int d = i >> 5, q4 = (i & 31) << 2;
        CPA(sb + OFF_STG + (uint32_t)(d * 128 + q4) * 4,
            Qg + (size_t)d * L_DIM + q0 + q4);
    }
    CP_COMMIT(); CP_WAIT0();
    __syncthreads();

    uint32_t qh[4][4], ql[4][4];
    {
        const float* Qst = (const float*)(sm + OFF_STG);
        #pragma unroll
        for (int ks = 0; ks < 4; ks++) {
            #pragma unroll
            for (int hf = 0; hf < 2; hf++) {
                int d0 = ks * 16 + c2 + hf * 8;
                float v00 = Qst[(d0+0)*128 + r0] * 0.125f;
                float v01 = Qst[(d0+1)*128 + r0] * 0.125f;
                float v10 = Qst[(d0+0)*128 + r1] * 0.125f;
                float v11 = Qst[(d0+1)*128 + r1] * 0.125f;
                __nv_bfloat16 ha,la,hb,lb;
                bsplit(v00, ha, la); bsplit(v01, hb, lb);
                qh[ks][hf*2+0] = pack2(ha, hb); ql[ks][hf*2+0] = pack2(la, lb);
                bsplit(v10, ha, la); bsplit(v11, hb, lb);
                qh[ks][hf*2+1] = pack2(ha, hb); ql[ks][hf*2+1] = pack2(la, lb);
            }
        }
    }
    __syncthreads();

    // ---- tile 0: stage + convert ----
    stage_kv(sb, Kg, Vg, 0, tid);
    CP_WAIT0();
    __syncthreads();
    convert_kv(sm, tid);
    __syncthreads();

    float o[8][4] = {};
    float lsum0 = 0.f, lsum1 = 0.f;

    for (int t = 0; t < 64; t++) {
        if (t + 1 < 64) stage_kv(sb, Kg, Vg, (t + 1) << 6, tid);

        // ---- S = Q K^T (3-pass split) ----
        float s[8][4] = {};
        #pragma unroll
        for (int nt = 0; nt < 8; nt++) {
            const uint32_t nrow = (uint32_t)(nt * 8 + lg) * 128;
            #pragma unroll
            for (int ks = 0; ks < 4; ks++) {
                uint32_t o0 = SWZ(nrow + (uint32_t)(ks*16 + c2) * 2);
                uint32_t o1 = SWZ(nrow + (uint32_t)(ks*16 + c2 + 8) * 2);
                uint32_t bh0 = *(const uint32_t*)(sm + OFF_KH + o0);
                uint32_t bh1 = *(const uint32_t*)(sm + OFF_KH + o1);
                uint32_t bl0 = *(const uint32_t*)(sm + OFF_KL + o0);
                uint32_t bl1 = *(const uint32_t*)(sm + OFF_KL + o1);
                mma_bf16(s[nt], qh[ks], bh0, bh1);
                mma_bf16(s[nt], qh[ks], bl0, bl1);
                mma_bf16(s[nt], ql[ks], bh0, bh1);
            }
        }

        // ---- softmax (no max subtraction) + P fragment packing ----
        uint32_t ph[4][4], pl[4][4];
        #pragma unroll
        for (int nt = 0; nt < 8; nt++) {
            s[nt][0] = fastexp(s[nt][0]); s[nt][1] = fastexp(s[nt][1]);
            s[nt][2] = fastexp(s[nt][2]); s[nt][3] = fastexp(s[nt][3]);
            lsum0 += s[nt][0] + s[nt][1];
            lsum1 += s[nt][2] + s[nt][3];
        }
        #pragma unroll
        for (int kt = 0; kt < 4; kt++) {
            __nv_bfloat16 ha,la,hb,lb;
            bsplit(s[2*kt][0], ha, la);   bsplit(s[2*kt][1], hb, lb);
            ph[kt][0] = pack2(ha,hb);     pl[kt][0] = pack2(la,lb);
            bsplit(s[2*kt][2], ha, la);   bsplit(s[2*kt][3], hb, lb);
            ph[kt][1] = pack2(ha,hb);     pl[kt][1] = pack2(la,lb);
            bsplit(s[2*kt+1][0], ha, la); bsplit(s[2*kt+1][1], hb, lb);
            ph[kt][2] = pack2(ha,hb);     pl[kt][2] = pack2(la,lb);
            bsplit(s[2*kt+1][2], ha, la); bsplit(s[2*kt+1][3], hb, lb);
            ph[kt][3] = pack2(ha,hb);     pl[kt][3] = pack2(la,lb);
        }

        // ---- O += P V^T (3-pass split) ----
        #pragma unroll
        for (int nt = 0; nt < 8; nt++) {
            const uint32_t nrow = (uint32_t)(nt * 8 + lg) * 128;
            #pragma unroll
            for (int kt = 0; kt < 4; kt++) {
                uint32_t o0 = SWZ(nrow + (uint32_t)(kt*16 + c2) * 2);
                uint32_t o1 = SWZ(nrow + (uint32_t)(kt*16 + c2 + 8) * 2);
                uint32_t vh0 = *(const uint32_t*)(sm + OFF_VH + o0);
                uint32_t vh1 = *(const uint32_t*)(sm + OFF_VH + o1);
                uint32_t vl0 = *(const uint32_t*)(sm + OFF_VL + o0);
                uint32_t vl1 = *(const uint32_t*)(sm + OFF_VL + o1);
                mma_bf16(o[nt], ph[kt], vh0, vh1);
                mma_bf16(o[nt], ph[kt], vl0, vl1);
                mma_bf16(o[nt], pl[kt], vh0, vh1);
            }
        }

        if (t + 1 < 64) {
            CP_WAIT0();
            __syncthreads();       // stage(t+1) landed; all warps done with bf16 bufs
            convert_kv(sm, tid);
            __syncthreads();
        }
    }

    // ---- row-sum reduce across the 4 lanes sharing a row ----
    lsum0 += __shfl_xor_sync(0xffffffffu, lsum0, 1);
    lsum0 += __shfl_xor_sync(0xffffffffu, lsum0, 2);
    lsum1 += __shfl_xor_sync(0xffffffffu, lsum1, 1);
    lsum1 += __shfl_xor_sync(0xffffffffu, lsum1, 2);
    const float inv0 = 1.f / lsum0, inv1 = 1.f / lsum1;

    // ---- stage O (fp32) to smem [64 d][128 q], then coalesced store ----
    __syncthreads();               // everyone done with K/V/stage smem
    float* Osm = (float*)sm;
    #pragma unroll
    for (int nt = 0; nt < 8; nt++) {
        int d = nt * 8 + c2;
        Osm[(d+0) * OPITCH + r0] = o[nt][0] * inv0;
        Osm[(d+1) * OPITCH + r0] = o[nt][1] * inv0;
        Osm[(d+0) * OPITCH + r1] = o[nt][2] * inv1;
        Osm[(d+1) * OPITCH + r1] = o[nt][3] * inv1;
    }
    __syncthreads();
    float* attbh = att + ((size_t)b * C_DIM + (size_t)h * HDIM) * L_DIM;
    #pragma unroll
    for (int it = 0; it < 8; it++) {
        int i = tid + it * 256;    // 0..2047
        int d = i >> 5, q4 = (i & 31) << 2;
        float4 v = *(const float4*)(Osm + d * OPITCH + q4);
        *(float4*)(attbh + (size_t)d * L_DIM + q0 + q4) = v;
    }
}

// ============================================================
// launch
// ============================================================
extern "C" void kernel_launch(void* const* d_in, const int* in_sizes, int n_in,
                              void* d_out, int out_size)
{
    const float* x    = (const float*)d_in[0];
    const float* gnw  = (const float*)d_in[1];
    const float* gnb  = (const float*)d_in[2];
    const float* qkvw = (const float*)d_in[3];
    const float* qkvb = (const float*)d_in[4];
    const float* pw   = (const float*)d_in[5];
    const float* pb   = (const float*)d_in[6];
    float* out = (float*)d_out;

    void* p;
    cudaGetSymbolAddress(&p, g_xn);  float* xn  = (float*)p;
    cudaGetSymbolAddress(&p, g_qkv); float* qkv = (float*)p;
    cudaGetSymbolAddress(&p, g_att); float* att = (float*)p;

    gn_kernel<<<BATCH * N_GROUPS, 256>>>(x, gnw, gnb, xn);

    gemm_kernel<<<dim3(L_DIM / 64, (3 * C_DIM) / 64, BATCH), 256>>>(
        qkvw, xn, qkvb, nullptr, qkv, 3 * C_DIM, C_DIM, L_DIM);

    cudaFuncSetAttribute(attn_mma,
                         cudaFuncAttributeMaxDynamicSharedMemorySize, SMEM_ATTN);
    attn_mma<<<dim3(L_DIM / 128, BATCH * NHEADS), 256, SMEM_ATTN>>>(qkv, att);

    gemm_kernel<<<dim3(L_DIM / 64, C_DIM / 64, BATCH), 256>>>(
        pw, att, pb, x, out, C_DIM, C_DIM, L_DIM);
}

// round 5
// speedup vs baseline: 2.6265x; 1.3485x over previous
#include <cuda_runtime.h>
#include <cuda_bf16.h>
#include <cstdint>

#define BATCH   2
#define C_DIM   256
#define L_DIM   4096
#define N_GROUPS 32
#define CPG     8
#define NHEADS  4
#define HDIM    64
#define EPS_GN  1e-5f

__device__ float g_xn [BATCH * C_DIM * L_DIM];
__device__ float g_qkv[BATCH * 3 * C_DIM * L_DIM];
__device__ float g_att[BATCH * C_DIM * L_DIM];
// pre-converted K/V tiles: per (bh, tile): KH 8KB | KL 8KB | VH 8KB | VL 8KB
__device__ uint8_t g_kvt[BATCH * NHEADS * 64 * 4 * 8192];

// ============================================================
// GroupNorm
// ============================================================
__global__ __launch_bounds__(256) void gn_kernel(const float* __restrict__ x,
                                                 const float* __restrict__ w,
                                                 const float* __restrict__ bias,
                                                 float* __restrict__ out)
{
    const int b = blockIdx.x >> 5;
    const int g = blockIdx.x & 31;
    const size_t base = ((size_t)b * C_DIM + (size_t)g * CPG) * L_DIM;
    const float4* xp = (const float4*)(x + base);
    float4*       op = (float4*)(out + base);
    const int tid = threadIdx.x;
    const int n4  = CPG * L_DIM / 4;

    float s = 0.f, sq = 0.f;
    #pragma unroll 4
    for (int i = tid; i < n4; i += 256) {
        float4 v = xp[i];
        s  += v.x + v.y + v.z + v.w;
        sq += v.x*v.x + v.y*v.y + v.z*v.z + v.w*v.w;
    }
    #pragma unroll
    for (int m = 16; m; m >>= 1) {
        s  += __shfl_xor_sync(0xffffffffu, s,  m);
        sq += __shfl_xor_sync(0xffffffffu, sq, m);
    }
    __shared__ float sa[8], sb[8], stats[2];
    if ((tid & 31) == 0) { sa[tid >> 5] = s; sb[tid >> 5] = sq; }
    __syncthreads();
    if (tid == 0) {
        float ts = 0.f, tq = 0.f;
        #pragma unroll
        for (int i = 0; i < 8; i++) { ts += sa[i]; tq += sb[i]; }
        const float inv_n = 1.f / (float)(CPG * L_DIM);
        float mean = ts * inv_n;
        float var  = tq * inv_n - mean * mean;
        stats[0] = mean;
        stats[1] = rsqrtf(var + EPS_GN);
    }
    __syncthreads();
    const float mean = stats[0], rstd = stats[1];
    #pragma unroll 4
    for (int i = tid; i < n4; i += 256) {
        int cloc = i >> 10;
        int c = g * CPG + cloc;
        float ww = w[c] * rstd;
        float bb = bias[c] - mean * ww;
        float4 v = xp[i];
        v.x = v.x * ww + bb; v.y = v.y * ww + bb;
        v.z = v.z * ww + bb; v.w = v.w * ww + bb;
        op[i] = v;
    }
}

// ============================================================
// SGEMM 128x128 tile, BK=8, 256 threads, 8x8 micro-tile (split quads,
// conflict-free smem reads).
// ============================================================
__global__ __launch_bounds__(256) void gemm128(const float* __restrict__ A,
                                               const float* __restrict__ Bm,
                                               const float* __restrict__ bias,
                                               const float* __restrict__ resid,
                                               float* __restrict__ Cm,
                                               int M, int K, int N)
{
    __shared__ float As[8][128];
    __shared__ float Bs[8][128];
    const int bz = blockIdx.z;
    const float* Bp = Bm + (size_t)bz * K * N;
    float*       Cp = Cm + (size_t)bz * M * N;
    const int m0 = blockIdx.y * 128, n0 = blockIdx.x * 128;
    const int tid = threadIdx.x;
    const int tx = tid & 15, ty = tid >> 4;
    const int am = tid >> 1, ak = (tid & 1) * 4;     // A: 128 m x 8 k
    const int bk = tid >> 5, bn = (tid & 31) * 4;    // B: 8 k x 128 n

    float acc[8][8] = {};
    for (int k0 = 0; k0 < K; k0 += 8) {
        float4 a = *(const float4*)(A + (size_t)(m0 + am) * K + k0 + ak);
        As[ak + 0][am] = a.x; As[ak + 1][am] = a.y;
        As[ak + 2][am] = a.z; As[ak + 3][am] = a.w;
        *(float4*)&Bs[bk][bn] =
            *(const float4*)(Bp + (size_t)(k0 + bk) * N + n0 + bn);
        __syncthreads();
        #pragma unroll
        for (int k = 0; k < 8; k++) {
            float av[8], bv[8];
            *(float4*)&av[0] = *(const float4*)&As[k][ty * 4];
            *(float4*)&av[4] = *(const float4*)&As[k][64 + ty * 4];
            *(float4*)&bv[0] = *(const float4*)&Bs[k][tx * 4];
            *(float4*)&bv[4] = *(const float4*)&Bs[k][64 + tx * 4];
            #pragma unroll
            for (int i = 0; i < 8; i++)
                #pragma unroll
                for (int j = 0; j < 8; j++)
                    acc[i][j] = fmaf(av[i], bv[j], acc[i][j]);
        }
        __syncthreads();
    }
    #pragma unroll
    for (int ih = 0; ih < 2; ih++) {
        #pragma unroll
        for (int i = 0; i < 4; i++) {
            const int m = m0 + ih * 64 + ty * 4 + i;
            const float bi = bias[m];
            const int ai = ih * 4 + i;
            #pragma unroll
            for (int jh = 0; jh < 2; jh++) {
                const int n = n0 + jh * 64 + tx * 4;
                float4 r = make_float4(acc[ai][jh*4+0] + bi, acc[ai][jh*4+1] + bi,
                                       acc[ai][jh*4+2] + bi, acc[ai][jh*4+3] + bi);
                if (resid) {
                    float4 rv = *(const float4*)(resid + (size_t)bz * M * N +
                                                 (size_t)m * N + n);
                    r.x += rv.x; r.y += rv.y; r.z += rv.z; r.w += rv.w;
                }
                *(float4*)(Cp + (size_t)m * N + n) = r;
            }
        }
    }
}

// ============================================================
// helpers
// ============================================================
__device__ __forceinline__ uint32_t smem_u32(const void* p) {
    uint32_t a;
    asm("{ .reg .u64 t; cvta.to.shared.u64 t, %1; cvt.u32.u64 %0, t; }"
        : "=r"(a) : "l"(p));
    return a;
}
__device__ __forceinline__ void mma_bf16(float* d, const uint32_t* a,
                                         uint32_t b0, uint32_t b1) {
    asm volatile(
        "mma.sync.aligned.m16n8k16.row.col.f32.bf16.bf16.f32 "
        "{%0,%1,%2,%3}, {%4,%5,%6,%7}, {%8,%9}, {%0,%1,%2,%3};\n"
        : "+f"(d[0]), "+f"(d[1]), "+f"(d[2]), "+f"(d[3])
        : "r"(a[0]), "r"(a[1]), "r"(a[2]), "r"(a[3]), "r"(b0), "r"(b1));
}
#define CPA(dst, src) \
    asm volatile("cp.async.cg.shared.global [%0], [%1], 16;" \
                 :: "r"(dst), "l"(src) : "memory")
#define CP_COMMIT() asm volatile("cp.async.commit_group;" ::: "memory")
#define CP_WAIT0()  asm volatile("cp.async.wait_group 0;" ::: "memory")
#define SWZ(o) ((o) ^ (((o) >> 3) & 0x70))

__device__ __forceinline__ float fastexp(float x) {
    x = fminf(fmaxf(x, -60.f), 60.f);
    float y = x * 1.4426950408889634f;
    float t = y + 12582912.f;
    int   n = __float_as_int(t) - 0x4B400000;
    float f = y - (t - 12582912.f);
    float p =           1.3333558146e-3f;
    p = fmaf(p, f, 9.6181291076e-3f);
    p = fmaf(p, f, 5.5504108665e-2f);
    p = fmaf(p, f, 2.4022650696e-1f);
    p = fmaf(p, f, 6.9314718056e-1f);
    p = fmaf(p, f, 1.0f);
    return p * __int_as_float((n + 127) << 23);
}
__device__ __forceinline__ uint32_t pack2(__nv_bfloat16 a, __nv_bfloat16 b) {
    __nv_bfloat162 t = __halves2bfloat162(a, b);
    return *reinterpret_cast<uint32_t*>(&t);
}
__device__ __forceinline__ void bsplit(float v, __nv_bfloat16& h, __nv_bfloat16& l) {
    h = __float2bfloat16_rn(v);
    l = __float2bfloat16_rn(v - __bfloat162float(h));
}

// ============================================================
// conv_kv: one-shot fp32 -> swizzled bf16 hi/lo tile images for K^T and V.
// grid (64 tiles, 8 bh), 256 threads.
// ============================================================
__global__ __launch_bounds__(256) void conv_kv(const float* __restrict__ qkv,
                                               uint8_t* __restrict__ out)
{
    __shared__ float st[8192];       // K raw [64d][64k] @0, V raw @4096
    const int t = blockIdx.x, bh = blockIdx.y;
    const int b = bh >> 2, h = bh & 3;
    const int n0 = t << 6;
    const float* Kg = qkv + ((size_t)b * 3 * C_DIM + C_DIM     + h * HDIM) * L_DIM;
    const float* Vg = qkv + ((size_t)b * 3 * C_DIM + 2 * C_DIM + h * HDIM) * L_DIM;
    const int tid = threadIdx.x;
    const uint32_t sb = smem_u32(st);

    #pragma unroll
    for (int it = 0; it < 4; it++) {
        int i = tid + it * 256;
        int d = i >> 4, c4 = (i & 15) << 2;
        CPA(sb + (uint32_t)(d * 64 + c4) * 4, Kg + (size_t)d * L_DIM + n0 + c4);
        CPA(sb + 16384u + (uint32_t)(d * 64 + c4) * 4,
            Vg + (size_t)d * L_DIM + n0 + c4);
    }
    CP_COMMIT(); CP_WAIT0();
    __syncthreads();

    uint8_t* dst = out + (size_t)(bh * 64 + t) * 32768;
    // ---- K^T: out row = key r, cols = d (hi @0, lo @8192) ----
    {
        const int r = tid >> 2, db = (tid & 3) << 4;
        uint32_t hb[8], lb[8];
        #pragma unroll
        for (int j = 0; j < 8; j++) {
            float a = st[(db + 2*j    ) * 64 + r];
            float c = st[(db + 2*j + 1) * 64 + r];
            __nv_bfloat16 ha, la, hc, lc;
            bsplit(a, ha, la); bsplit(c, hc, lc);
            hb[j] = pack2(ha, hc); lb[j] = pack2(la, lc);
        }
        const uint32_t o0 = SWZ((uint32_t)r * 128 + db * 2);
        const uint32_t o1 = SWZ((uint32_t)r * 128 + db * 2 + 16);
        *(uint4*)(dst + o0)        = make_uint4(hb[0], hb[1], hb[2], hb[3]);
        *(uint4*)(dst + o1)        = make_uint4(hb[4], hb[5], hb[6], hb[7]);
        *(uint4*)(dst + 8192 + o0) = make_uint4(lb[0], lb[1], lb[2], lb[3]);
        *(uint4*)(dst + 8192 + o1) = make_uint4(lb[4], lb[5], lb[6], lb[7]);
    }
    // ---- V: out row = d, cols = key (hi @16384, lo @24576) ----
    {
        const float* Vst = st + 4096;
        const int d = tid >> 2, kb = (tid & 3) << 4;
        uint32_t hb[8], lb[8];
        #pragma unroll
        for (int j = 0; j < 8; j++) {
            float a = Vst[d * 64 + kb + 2*j];
            float c = Vst[d * 64 + kb + 2*j + 1];
            __nv_bfloat16 ha, la, hc, lc;
            bsplit(a, ha, la); bsplit(c, hc, lc);
            hb[j] = pack2(ha, hc); lb[j] = pack2(la, lc);
        }
        const uint32_t o0 = SWZ((uint32_t)d * 128 + kb * 2);
        const uint32_t o1 = SWZ((uint32_t)d * 128 + kb * 2 + 16);
        *(uint4*)(dst + 16384 + o0) = make_uint4(hb[0], hb[1], hb[2], hb[3]);
        *(uint4*)(dst + 16384 + o1) = make_uint4(hb[4], hb[5], hb[6], hb[7]);
        *(uint4*)(dst + 24576 + o0) = make_uint4(lb[0], lb[1], lb[2], lb[3]);
        *(uint4*)(dst + 24576 + o1) = make_uint4(lb[4], lb[5], lb[6], lb[7]);
    }
}

// ============================================================
// mma.sync flash attention, pre-converted K/V tiles, double-buffered.
// CTA: 128 queries x (b,h); 8 warps x 16 query rows.
// ============================================================
#define SMEM_ATTN 65536
#define OPITCH 132

__global__ __launch_bounds__(256) void attn_mma(const float* __restrict__ qkv,
                                                const uint8_t* __restrict__ kvt,
                                                float* __restrict__ att)
{
    extern __shared__ char sm[];
    const uint32_t sb = smem_u32(sm);
    const int tid = threadIdx.x;
    const int w = tid >> 5, l = tid & 31;
    const int lg = l >> 2;
    const int c2 = (l & 3) * 2;
    const int r0 = w * 16 + lg;
    const int r1 = r0 + 8;

    const int bh = blockIdx.y, b = bh >> 2, h = bh & 3;
    const int q0 = blockIdx.x << 7;
    const float* Qg = qkv + ((size_t)b * 3 * C_DIM + (size_t)h * HDIM) * L_DIM;
    const uint8_t* kvbh = kvt + (size_t)bh * 64 * 32768;

    // ---- prologue: stage Q raw [64 d][128 q] into buf0, build A fragments ----
    #pragma unroll
    for (int it = 0; it < 8; it++) {
        int i = tid + it * 256;
        int d = i >> 5, q4 = (i & 31) << 2;
        CPA(sb + (uint32_t)(d * 128 + q4) * 4, Qg + (size_t)d * L_DIM + q0 + q4);
    }
    CP_COMMIT(); CP_WAIT0();
    __syncthreads();

    uint32_t qh[4][4], ql[4][4];
    {
        const float* Qst = (const float*)sm;
        #pragma unroll
        for (int ks = 0; ks < 4; ks++) {
            #pragma unroll
            for (int hf = 0; hf < 2; hf++) {
                int d0 = ks * 16 + c2 + hf * 8;
                float v00 = Qst[(d0+0)*128 + r0] * 0.125f;
                float v01 = Qst[(d0+1)*128 + r0] * 0.125f;
                float v10 = Qst[(d0+0)*128 + r1] * 0.125f;
                float v11 = Qst[(d0+1)*128 + r1] * 0.125f;
                __nv_bfloat16 ha,la,hb,lb;
                bsplit(v00, ha, la); bsplit(v01, hb, lb);
                qh[ks][hf*2+0] = pack2(ha, hb); ql[ks][hf*2+0] = pack2(la, lb);
                bsplit(v10, ha, la); bsplit(v11, hb, lb);
                qh[ks][hf*2+1] = pack2(ha, hb); ql[ks][hf*2+1] = pack2(la, lb);
            }
        }
    }
    __syncthreads();

    // ---- stage tile 0 into buf0 ----
    #pragma unroll
    for (int it = 0; it < 8; it++) {
        int i = tid + it * 256;
        CPA(sb + (uint32_t)i * 16, kvbh + (size_t)i * 16);
    }
    CP_COMMIT();

    float o[8][4] = {};
    float lsum0 = 0.f, lsum1 = 0.f;

    for (int t = 0; t < 64; t++) {
        CP_WAIT0();
        __syncthreads();     // tile t visible; prior compute done everywhere
        if (t + 1 < 64) {
            const uint32_t db = ((t + 1) & 1) * 32768u;
            const uint8_t* src = kvbh + (size_t)(t + 1) * 32768;
            #pragma unroll
            for (int it = 0; it < 8; it++) {
                int i = tid + it * 256;
                CPA(sb + db + (uint32_t)i * 16, src + (size_t)i * 16);
            }
            CP_COMMIT();
        }
        const char* bb = sm + (t & 1) * 32768;

        // ---- S = Q K^T (3-pass split) ----
        float s[8][4] = {};
        #pragma unroll
        for (int nt = 0; nt < 8; nt++) {
            const uint32_t nrow = (uint32_t)(nt * 8 + lg) * 128;
            #pragma unroll
            for (int ks = 0; ks < 4; ks++) {
                uint32_t o0 = SWZ(nrow + (uint32_t)(ks*16 + c2) * 2);
                uint32_t o1 = SWZ(nrow + (uint32_t)(ks*16 + c2 + 8) * 2);
                uint32_t bh0 = *(const uint32_t*)(bb + o0);
                uint32_t bh1 = *(const uint32_t*)(bb + o1);
                uint32_t bl0 = *(const uint32_t*)(bb + 8192 + o0);
                uint32_t bl1 = *(const uint32_t*)(bb + 8192 + o1);
                mma_bf16(s[nt], qh[ks], bh0, bh1);
                mma_bf16(s[nt], qh[ks], bl0, bl1);
                mma_bf16(s[nt], ql[ks], bh0, bh1);
            }
        }

        // ---- softmax (no max subtraction) + P packing ----
        uint32_t ph[4][4], pl[4][4];
        #pragma unroll
        for (int nt = 0; nt < 8; nt++) {
            s[nt][0] = fastexp(s[nt][0]); s[nt][1] = fastexp(s[nt][1]);
            s[nt][2] = fastexp(s[nt][2]); s[nt][3] = fastexp(s[nt][3]);
            lsum0 += s[nt][0] + s[nt][1];
            lsum1 += s[nt][2] + s[nt][3];
        }
        #pragma unroll
        for (int kt = 0; kt < 4; kt++) {
            __nv_bfloat16 ha,la,hb,lb;
            bsplit(s[2*kt][0], ha, la);   bsplit(s[2*kt][1], hb, lb);
            ph[kt][0] = pack2(ha,hb);     pl[kt][0] = pack2(la,lb);
            bsplit(s[2*kt][2], ha, la);   bsplit(s[2*kt][3], hb, lb);
            ph[kt][1] = pack2(ha,hb);     pl[kt][1] = pack2(la,lb);
            bsplit(s[2*kt+1][0], ha, la); bsplit(s[2*kt+1][1], hb, lb);
            ph[kt][2] = pack2(ha,hb);     pl[kt][2] = pack2(la,lb);
            bsplit(s[2*kt+1][2], ha, la); bsplit(s[2*kt+1][3], hb, lb);
            ph[kt][3] = pack2(ha,hb);     pl[kt][3] = pack2(la,lb);
        }

        // ---- O += P V^T (3-pass split) ----
        #pragma unroll
        for (int nt = 0; nt < 8; nt++) {
            const uint32_t nrow = (uint32_t)(nt * 8 + lg) * 128;
            #pragma unroll
            for (int kt = 0; kt < 4; kt++) {
                uint32_t o0 = SWZ(nrow + (uint32_t)(kt*16 + c2) * 2);
                uint32_t o1 = SWZ(nrow + (uint32_t)(kt*16 + c2 + 8) * 2);
                uint32_t vh0 = *(const uint32_t*)(bb + 16384 + o0);
                uint32_t vh1 = *(const uint32_t*)(bb + 16384 + o1);
                uint32_t vl0 = *(const uint32_t*)(bb + 24576 + o0);
                uint32_t vl1 = *(const uint32_t*)(bb + 24576 + o1);
                mma_bf16(o[nt], ph[kt], vh0, vh1);
                mma_bf16(o[nt], ph[kt], vl0, vl1);
                mma_bf16(o[nt], pl[kt], vh0, vh1);
            }
        }
    }

    // ---- reduce row sums across quad lanes ----
    lsum0 += __shfl_xor_sync(0xffffffffu, lsum0, 1);
    lsum0 += __shfl_xor_sync(0xffffffffu, lsum0, 2);
    lsum1 += __shfl_xor_sync(0xffffffffu, lsum1, 1);
    lsum1 += __shfl_xor_sync(0xffffffffu, lsum1, 2);
    const float inv0 = 1.f / lsum0, inv1 = 1.f / lsum1;

    // ---- stage O to smem [64 d][128 q], coalesced store ----
    __syncthreads();
    float* Osm = (float*)sm;
    #pragma unroll
    for (int nt = 0; nt < 8; nt++) {
        int d = nt * 8 + c2;
        Osm[(d+0) * OPITCH + r0] = o[nt][0] * inv0;
        Osm[(d+1) * OPITCH + r0] = o[nt][1] * inv0;
        Osm[(d+0) * OPITCH + r1] = o[nt][2] * inv1;
        Osm[(d+1) * OPITCH + r1] = o[nt][3] * inv1;
    }
    __syncthreads();
    float* attbh = att + ((size_t)b * C_DIM + (size_t)h * HDIM) * L_DIM;
    #pragma unroll
    for (int it = 0; it < 8; it++) {
        int i = tid + it * 256;
        int d = i >> 5, q4 = (i & 31) << 2;
        float4 v = *(const float4*)(Osm + d * OPITCH + q4);
        *(float4*)(attbh + (size_t)d * L_DIM + q0 + q4) = v;
    }
}

// ============================================================
// launch
// ============================================================
extern "C" void kernel_launch(void* const* d_in, const int* in_sizes, int n_in,
                              void* d_out, int out_size)
{
    const float* x    = (const float*)d_in[0];
    const float* gnw  = (const float*)d_in[1];
    const float* gnb  = (const float*)d_in[2];
    const float* qkvw = (const float*)d_in[3];
    const float* qkvb = (const float*)d_in[4];
    const float* pw   = (const float*)d_in[5];
    const float* pb   = (const float*)d_in[6];
    float* out = (float*)d_out;

    void* p;
    cudaGetSymbolAddress(&p, g_xn);  float* xn  = (float*)p;
    cudaGetSymbolAddress(&p, g_qkv); float* qkv = (float*)p;
    cudaGetSymbolAddress(&p, g_att); float* att = (float*)p;
    cudaGetSymbolAddress(&p, g_kvt); uint8_t* kvt = (uint8_t*)p;

    gn_kernel<<<BATCH * N_GROUPS, 256>>>(x, gnw, gnb, xn);

    gemm128<<<dim3(L_DIM / 128, (3 * C_DIM) / 128, BATCH), 256>>>(
        qkvw, xn, qkvb, nullptr, qkv, 3 * C_DIM, C_DIM, L_DIM);

    conv_kv<<<dim3(64, BATCH * NHEADS), 256>>>(qkv, kvt);

    cudaFuncSetAttribute(attn_mma,
                         cudaFuncAttributeMaxDynamicSharedMemorySize, SMEM_ATTN);
    attn_mma<<<dim3(L_DIM / 128, BATCH * NHEADS), 256, SMEM_ATTN>>>(qkv, kvt, att);

    gemm128<<<dim3(L_DIM / 128, C_DIM / 128, BATCH), 256>>>(
        pw, att, pb, x, out, C_DIM, C_DIM, L_DIM);
}

// round 7
// speedup vs baseline: 3.1297x; 1.1916x over previous
#include <cuda_runtime.h>
#include <cuda_fp16.h>
#include <cuda_bf16.h>
#include <cstdint>

#define BATCH   2
#define C_DIM   256
#define L_DIM   4096
#define N_GROUPS 32
#define CPG     8
#define NHEADS  4
#define HDIM    64
#define EPS_GN  1e-5f

__device__ float g_xn [BATCH * C_DIM * L_DIM];
__device__ float g_qkv[BATCH * 3 * C_DIM * L_DIM];
__device__ float g_att[BATCH * C_DIM * L_DIM];
// pre-converted K/V tiles: per (bh, tile): KH 8KB | VH 8KB | VL 8KB
#define TILE_B 24576
__device__ uint8_t g_kvt[BATCH * NHEADS * 64 * TILE_B];

// ============================================================
// GroupNorm
// ============================================================
__global__ __launch_bounds__(256) void gn_kernel(const float* __restrict__ x,
                                                 const float* __restrict__ w,
                                                 const float* __restrict__ bias,
                                                 float* __restrict__ out)
{
    const int b = blockIdx.x >> 5;
    const int g = blockIdx.x & 31;
    const size_t base = ((size_t)b * C_DIM + (size_t)g * CPG) * L_DIM;
    const float4* xp = (const float4*)(x + base);
    float4*       op = (float4*)(out + base);
    const int tid = threadIdx.x;
    const int n4  = CPG * L_DIM / 4;

    float s = 0.f, sq = 0.f;
    #pragma unroll 4
    for (int i = tid; i < n4; i += 256) {
        float4 v = xp[i];
        s  += v.x + v.y + v.z + v.w;
        sq += v.x*v.x + v.y*v.y + v.z*v.z + v.w*v.w;
    }
    #pragma unroll
    for (int m = 16; m; m >>= 1) {
        s  += __shfl_xor_sync(0xffffffffu, s,  m);
        sq += __shfl_xor_sync(0xffffffffu, sq, m);
    }
    __shared__ float sa[8], sb[8], stats[2];
    if ((tid & 31) == 0) { sa[tid >> 5] = s; sb[tid >> 5] = sq; }
    __syncthreads();
    if (tid == 0) {
        float ts = 0.f, tq = 0.f;
        #pragma unroll
        for (int i = 0; i < 8; i++) { ts += sa[i]; tq += sb[i]; }
        const float inv_n = 1.f / (float)(CPG * L_DIM);
        float mean = ts * inv_n;
        float var  = tq * inv_n - mean * mean;
        stats[0] = mean;
        stats[1] = rsqrtf(var + EPS_GN);
    }
    __syncthreads();
    const float mean = stats[0], rstd = stats[1];
    #pragma unroll 4
    for (int i = tid; i < n4; i += 256) {
        int cloc = i >> 10;
        int c = g * CPG + cloc;
        float ww = w[c] * rstd;
        float bb = bias[c] - mean * ww;
        float4 v = xp[i];
        v.x = v.x * ww + bb; v.y = v.y * ww + bb;
        v.z = v.z * ww + bb; v.w = v.w * ww + bb;
        op[i] = v;
    }
}

// ============================================================
// SGEMM 128x128 tile, BK=8, 256 threads, 8x8 micro-tile
// ============================================================
__global__ __launch_bounds__(256) void gemm128(const float* __restrict__ A,
                                               const float* __restrict__ Bm,
                                               const float* __restrict__ bias,
                                               const float* __restrict__ resid,
                                               float* __restrict__ Cm,
                                               int M, int K, int N)
{
    __shared__ float As[8][128];
    __shared__ float Bs[8][128];
    const int bz = blockIdx.z;
    const float* Bp = Bm + (size_t)bz * K * N;
    float*       Cp = Cm + (size_t)bz * M * N;
    const int m0 = blockIdx.y * 128, n0 = blockIdx.x * 128;
    const int tid = threadIdx.x;
    const int tx = tid & 15, ty = tid >> 4;
    const int am = tid >> 1, ak = (tid & 1) * 4;
    const int bk = tid >> 5, bn = (tid & 31) * 4;

    float acc[8][8] = {};
    for (int k0 = 0; k0 < K; k0 += 8) {
        float4 a = *(const float4*)(A + (size_t)(m0 + am) * K + k0 + ak);
        As[ak + 0][am] = a.x; As[ak + 1][am] = a.y;
        As[ak + 2][am] = a.z; As[ak + 3][am] = a.w;
        *(float4*)&Bs[bk][bn] =
            *(const float4*)(Bp + (size_t)(k0 + bk) * N + n0 + bn);
        __syncthreads();
        #pragma unroll
        for (int k = 0; k < 8; k++) {
            float av[8], bv[8];
            *(float4*)&av[0] = *(const float4*)&As[k][ty * 4];
            *(float4*)&av[4] = *(const float4*)&As[k][64 + ty * 4];
            *(float4*)&bv[0] = *(const float4*)&Bs[k][tx * 4];
            *(float4*)&bv[4] = *(const float4*)&Bs[k][64 + tx * 4];
            #pragma unroll
            for (int i = 0; i < 8; i++)
                #pragma unroll
                for (int j = 0; j < 8; j++)
                    acc[i][j] = fmaf(av[i], bv[j], acc[i][j]);
        }
        __syncthreads();
    }
    #pragma unroll
    for (int ih = 0; ih < 2; ih++) {
        #pragma unroll
        for (int i = 0; i < 4; i++) {
            const int m = m0 + ih * 64 + ty * 4 + i;
            const float bi = bias[m];
            const int ai = ih * 4 + i;
            #pragma unroll
            for (int jh = 0; jh < 2; jh++) {
                const int n = n0 + jh * 64 + tx * 4;
                float4 r = make_float4(acc[ai][jh*4+0] + bi, acc[ai][jh*4+1] + bi,
                                       acc[ai][jh*4+2] + bi, acc[ai][jh*4+3] + bi);
                if (resid) {
                    float4 rv = *(const float4*)(resid + (size_t)bz * M * N +
                                                 (size_t)m * N + n);
                    r.x += rv.x; r.y += rv.y; r.z += rv.z; r.w += rv.w;
                }
                *(float4*)(Cp + (size_t)m * N + n) = r;
            }
        }
    }
}

// ============================================================
// helpers
// ============================================================
__device__ __forceinline__ uint32_t smem_u32(const void* p) {
    uint32_t a;
    asm("{ .reg .u64 t; cvta.to.shared.u64 t, %1; cvt.u32.u64 %0, t; }"
        : "=r"(a) : "l"(p));
    return a;
}
__device__ __forceinline__ void mma_fp16(float* d, const uint32_t* a,
                                         uint32_t b0, uint32_t b1) {
    asm volatile(
        "mma.sync.aligned.m16n8k16.row.col.f32.f16.f16.f32 "
        "{%0,%1,%2,%3}, {%4,%5,%6,%7}, {%8,%9}, {%0,%1,%2,%3};\n"
        : "+f"(d[0]), "+f"(d[1]), "+f"(d[2]), "+f"(d[3])
        : "r"(a[0]), "r"(a[1]), "r"(a[2]), "r"(a[3]), "r"(b0), "r"(b1));
}
#define CPA(dst, src) \
    asm volatile("cp.async.cg.shared.global [%0], [%1], 16;" \
                 :: "r"(dst), "l"(src) : "memory")
#define CP_COMMIT() asm volatile("cp.async.commit_group;" ::: "memory")
#define CP_WAIT0()  asm volatile("cp.async.wait_group 0;" ::: "memory")
#define SWZ(o) ((o) ^ (((o) >> 3) & 0x70))

__device__ __forceinline__ float fastexp(float x) {
    x = fminf(fmaxf(x, -60.f), 60.f);
    float y = x * 1.4426950408889634f;
    float t = y + 12582912.f;
    int   n = __float_as_int(t) - 0x4B400000;
    float f = y - (t - 12582912.f);
    float p =           1.3333558146e-3f;
    p = fmaf(p, f, 9.6181291076e-3f);
    p = fmaf(p, f, 5.5504108665e-2f);
    p = fmaf(p, f, 2.4022650696e-1f);
    p = fmaf(p, f, 6.9314718056e-1f);
    p = fmaf(p, f, 1.0f);
    return p * __int_as_float((n + 127) << 23);
}
__device__ __forceinline__ uint32_t packh2(float a, float b) {
    __half2 t = __floats2half2_rn(a, b);   // low = a, high = b
    return *reinterpret_cast<uint32_t*>(&t);
}
__device__ __forceinline__ void hsplit(float v, __half& h, __half& l) {
    h = __float2half_rn(v);
    l = __float2half_rn(v - __half2float(h));
}
__device__ __forceinline__ uint32_t packhh(__half a, __half b) {
    __half2 t = __halves2half2(a, b);
    return *reinterpret_cast<uint32_t*>(&t);
}

// ============================================================
// conv_kv: fp32 -> fp16 tile images.  K^T hi-only; V hi/lo split.
// grid (64 tiles, 8 bh), 256 threads.
// ============================================================
__global__ __launch_bounds__(256) void conv_kv(const float* __restrict__ qkv,
                                               uint8_t* __restrict__ out)
{
    __shared__ float st[8192];       // K raw [64d][64k] @0, V raw @4096
    const int t = blockIdx.x, bh = blockIdx.y;
    const int b = bh >> 2, h = bh & 3;
    const int n0 = t << 6;
    const float* Kg = qkv + ((size_t)b * 3 * C_DIM + C_DIM     + h * HDIM) * L_DIM;
    const float* Vg = qkv + ((size_t)b * 3 * C_DIM + 2 * C_DIM + h * HDIM) * L_DIM;
    const int tid = threadIdx.x;
    const uint32_t sb = smem_u32(st);

    #pragma unroll
    for (int it = 0; it < 4; it++) {
        int i = tid + it * 256;
        int d = i >> 4, c4 = (i & 15) << 2;
        CPA(sb + (uint32_t)(d * 64 + c4) * 4, Kg + (size_t)d * L_DIM + n0 + c4);
        CPA(sb + 16384u + (uint32_t)(d * 64 + c4) * 4,
            Vg + (size_t)d * L_DIM + n0 + c4);
    }
    CP_COMMIT(); CP_WAIT0();
    __syncthreads();

    uint8_t* dst = out + (size_t)(bh * 64 + t) * TILE_B;
    // ---- K^T (hi only): row = key r, cols = d ----
    {
        const int r = tid >> 2, db = (tid & 3) << 4;
        uint32_t hb[8];
        #pragma unroll
        for (int j = 0; j < 8; j++) {
            float a = st[(db + 2*j    ) * 64 + r];
            float c = st[(db + 2*j + 1) * 64 + r];
            hb[j] = packh2(a, c);
        }
        const uint32_t o0 = SWZ((uint32_t)r * 128 + db * 2);
        const uint32_t o1 = SWZ((uint32_t)r * 128 + db * 2 + 16);
        *(uint4*)(dst + o0) = make_uint4(hb[0], hb[1], hb[2], hb[3]);
        *(uint4*)(dst + o1) = make_uint4(hb[4], hb[5], hb[6], hb[7]);
    }
    // ---- V hi/lo: row = d, cols = key (hi @8192, lo @16384) ----
    {
        const float* Vst = st + 4096;
        const int d = tid >> 2, kb = (tid & 3) << 4;
        uint32_t hb[8], lb[8];
        #pragma unroll
        for (int j = 0; j < 8; j++) {
            float a = Vst[d * 64 + kb + 2*j];
            float c = Vst[d * 64 + kb + 2*j + 1];
            __half ha, la, hc, lc;
            hsplit(a, ha, la); hsplit(c, hc, lc);
            hb[j] = packhh(ha, hc); lb[j] = packhh(la, lc);
        }
        const uint32_t o0 = SWZ((uint32_t)d * 128 + kb * 2);
        const uint32_t o1 = SWZ((uint32_t)d * 128 + kb * 2 + 16);
        *(uint4*)(dst + 8192  + o0) = make_uint4(hb[0], hb[1], hb[2], hb[3]);
        *(uint4*)(dst + 8192  + o1) = make_uint4(hb[4], hb[5], hb[6], hb[7]);
        *(uint4*)(dst + 16384 + o0) = make_uint4(lb[0], lb[1], lb[2], lb[3]);
        *(uint4*)(dst + 16384 + o1) = make_uint4(lb[4], lb[5], lb[6], lb[7]);
    }
}

// ============================================================
// fp16 4-pass flash attention with online max.
// CTA: 128 queries x (b,h); 8 warps x 16 query rows.
// ============================================================
#define SMEM_ATTN 49152
#define OPITCH 132

__global__ __launch_bounds__(256) void attn_mma(const float* __restrict__ qkv,
                                                const uint8_t* __restrict__ kvt,
                                                float* __restrict__ att)
{
    extern __shared__ char sm[];
    const uint32_t sb = smem_u32(sm);
    const int tid = threadIdx.x;
    const int w = tid >> 5, l = tid & 31;
    const int lg = l >> 2;
    const int c2 = (l & 3) * 2;
    const int r0 = w * 16 + lg;
    const int r1 = r0 + 8;

    const int bh = blockIdx.y, b = bh >> 2, h = bh & 3;
    const int q0 = blockIdx.x << 7;
    const float* Qg = qkv + ((size_t)b * 3 * C_DIM + (size_t)h * HDIM) * L_DIM;
    const uint8_t* kvbh = kvt + (size_t)bh * 64 * TILE_B;

    // ---- prologue: stage Q raw [64 d][128 q], build fp16 hi/lo fragments ----
    #pragma unroll
    for (int it = 0; it < 8; it++) {
        int i = tid + it * 256;
        int d = i >> 5, q4 = (i & 31) << 2;
        CPA(sb + (uint32_t)(d * 128 + q4) * 4, Qg + (size_t)d * L_DIM + q0 + q4);
    }
    CP_COMMIT(); CP_WAIT0();
    __syncthreads();

    uint32_t qh[4][4], ql[4][4];
    {
        const float* Qst = (const float*)sm;
        #pragma unroll
        for (int ks = 0; ks < 4; ks++) {
            #pragma unroll
            for (int hf = 0; hf < 2; hf++) {
                int d0 = ks * 16 + c2 + hf * 8;
                float v00 = Qst[(d0+0)*128 + r0] * 0.125f;
                float v01 = Qst[(d0+1)*128 + r0] * 0.125f;
                float v10 = Qst[(d0+0)*128 + r1] * 0.125f;
                float v11 = Qst[(d0+1)*128 + r1] * 0.125f;
                __half ha,la,hb_,lb_;
                hsplit(v00, ha, la); hsplit(v01, hb_, lb_);
                qh[ks][hf*2+0] = packhh(ha, hb_); ql[ks][hf*2+0] = packhh(la, lb_);
                hsplit(v10, ha, la); hsplit(v11, hb_, lb_);
                qh[ks][hf*2+1] = packhh(ha, hb_); ql[ks][hf*2+1] = packhh(la, lb_);
            }
        }
    }
    __syncthreads();

    // ---- stage tile 0 into buf0 ----
    #pragma unroll
    for (int it = 0; it < 6; it++) {
        int i = tid + it * 256;
        CPA(sb + (uint32_t)i * 16, kvbh + (size_t)i * 16);
    }
    CP_COMMIT();

    float o[8][4] = {};
    float lsum0 = 0.f, lsum1 = 0.f;
    float mrow0 = -1e30f, mrow1 = -1e30f;

    for (int t = 0; t < 64; t++) {
        CP_WAIT0();
        __syncthreads();
        if (t + 1 < 64) {
            const uint32_t db = ((t + 1) & 1) * (uint32_t)TILE_B;
            const uint8_t* src = kvbh + (size_t)(t + 1) * TILE_B;
            #pragma unroll
            for (int it = 0; it < 6; it++) {
                int i = tid + it * 256;
                CPA(sb + db + (uint32_t)i * 16, src + (size_t)i * 16);
            }
            CP_COMMIT();
        }
        const char* bb = sm + (t & 1) * TILE_B;

        // ---- S = Q K^T (2-pass: (qh + ql) x kh) ----
        float s[8][4] = {};
        #pragma unroll
        for (int nt = 0; nt < 8; nt++) {
            const uint32_t nrow = (uint32_t)(nt * 8 + lg) * 128;
            #pragma unroll
            for (int ks = 0; ks < 4; ks++) {
                uint32_t o0 = SWZ(nrow + (uint32_t)(ks*16 + c2) * 2);
                uint32_t o1 = SWZ(nrow + (uint32_t)(ks*16 + c2 + 8) * 2);
                uint32_t bh0 = *(const uint32_t*)(bb + o0);
                uint32_t bh1 = *(const uint32_t*)(bb + o1);
                mma_fp16(s[nt], qh[ks], bh0, bh1);
                mma_fp16(s[nt], ql[ks], bh0, bh1);
            }
        }

        // ---- online max softmax ----
        float tm0 = s[0][0], tm1 = s[0][2];
        tm0 = fmaxf(tm0, s[0][1]); tm1 = fmaxf(tm1, s[0][3]);
        #pragma unroll
        for (int nt = 1; nt < 8; nt++) {
            tm0 = fmaxf(tm0, fmaxf(s[nt][0], s[nt][1]));
            tm1 = fmaxf(tm1, fmaxf(s[nt][2], s[nt][3]));
        }
        tm0 = fmaxf(tm0, __shfl_xor_sync(0xffffffffu, tm0, 1));
        tm0 = fmaxf(tm0, __shfl_xor_sync(0xffffffffu, tm0, 2));
        tm1 = fmaxf(tm1, __shfl_xor_sync(0xffffffffu, tm1, 1));
        tm1 = fmaxf(tm1, __shfl_xor_sync(0xffffffffu, tm1, 2));
        const float m0n = fmaxf(mrow0, tm0), m1n = fmaxf(mrow1, tm1);
        const float a0 = fastexp(mrow0 - m0n), a1 = fastexp(mrow1 - m1n);
        mrow0 = m0n; mrow1 = m1n;
        lsum0 *= a0; lsum1 *= a1;

        uint32_t ph[4][4];
        #pragma unroll
        for (int nt = 0; nt < 8; nt++) {
            s[nt][0] = fastexp(s[nt][0] - m0n);
            s[nt][1] = fastexp(s[nt][1] - m0n);
            s[nt][2] = fastexp(s[nt][2] - m1n);
            s[nt][3] = fastexp(s[nt][3] - m1n);
            lsum0 += s[nt][0] + s[nt][1];
            lsum1 += s[nt][2] + s[nt][3];
            o[nt][0] *= a0; o[nt][1] *= a0;
            o[nt][2] *= a1; o[nt][3] *= a1;
        }
        #pragma unroll
        for (int kt = 0; kt < 4; kt++) {
            ph[kt][0] = packh2(s[2*kt][0],   s[2*kt][1]);
            ph[kt][1] = packh2(s[2*kt][2],   s[2*kt][3]);
            ph[kt][2] = packh2(s[2*kt+1][0], s[2*kt+1][1]);
            ph[kt][3] = packh2(s[2*kt+1][2], s[2*kt+1][3]);
        }

        // ---- O += P (vh + vl)  (2-pass) ----
        #pragma unroll
        for (int nt = 0; nt < 8; nt++) {
            const uint32_t nrow = (uint32_t)(nt * 8 + lg) * 128;
            #pragma unroll
            for (int kt = 0; kt < 4; kt++) {
                uint32_t o0 = SWZ(nrow + (uint32_t)(kt*16 + c2) * 2);
                uint32_t o1 = SWZ(nrow + (uint32_t)(kt*16 + c2 + 8) * 2);
                uint32_t vh0 = *(const uint32_t*)(bb + 8192  + o0);
                uint32_t vh1 = *(const uint32_t*)(bb + 8192  + o1);
                uint32_t vl0 = *(const uint32_t*)(bb + 16384 + o0);
                uint32_t vl1 = *(const uint32_t*)(bb + 16384 + o1);
                mma_fp16(o[nt], ph[kt], vh0, vh1);
                mma_fp16(o[nt], ph[kt], vl0, vl1);
            }
        }
    }

    // ---- reduce row sums across quad lanes ----
    lsum0 += __shfl_xor_sync(0xffffffffu, lsum0, 1);
    lsum0 += __shfl_xor_sync(0xffffffffu, lsum0, 2);
    lsum1 += __shfl_xor_sync(0xffffffffu, lsum1, 1);
    lsum1 += __shfl_xor_sync(0xffffffffu, lsum1, 2);
    const float inv0 = 1.f / lsum0, inv1 = 1.f / lsum1;

    // ---- stage O to smem [64 d][128 q], coalesced store ----
    __syncthreads();
    float* Osm = (float*)sm;
    #pragma unroll
    for (int nt = 0; nt < 8; nt++) {
        int d = nt * 8 + c2;
        Osm[(d+0) * OPITCH + r0] = o[nt][0] * inv0;
        Osm[(d+1) * OPITCH + r0] = o[nt][1] * inv0;
        Osm[(d+0) * OPITCH + r1] = o[nt][2] * inv1;
        Osm[(d+1) * OPITCH + r1] = o[nt][3] * inv1;
    }
    __syncthreads();
    float* attbh = att + ((size_t)b * C_DIM + (size_t)h * HDIM) * L_DIM;
    #pragma unroll
    for (int it = 0; it < 8; it++) {
        int i = tid + it * 256;
        int d = i >> 5, q4 = (i & 31) << 2;
        float4 v = *(const float4*)(Osm + d * OPITCH + q4);
        *(float4*)(attbh + (size_t)d * L_DIM + q0 + q4) = v;
    }
}

// ============================================================
// launch
// ============================================================
extern "C" void kernel_launch(void* const* d_in, const int* in_sizes, int n_in,
                              void* d_out, int out_size)
{
    const float* x    = (const float*)d_in[0];
    const float* gnw  = (const float*)d_in[1];
    const float* gnb  = (const float*)d_in[2];
    const float* qkvw = (const float*)d_in[3];
    const float* qkvb = (const float*)d_in[4];
    const float* pw   = (const float*)d_in[5];
    const float* pb   = (const float*)d_in[6];
    float* out = (float*)d_out;

    void* p;
    cudaGetSymbolAddress(&p, g_xn);  float* xn  = (float*)p;
    cudaGetSymbolAddress(&p, g_qkv); float* qkv = (float*)p;
    cudaGetSymbolAddress(&p, g_att); float* att = (float*)p;
    cudaGetSymbolAddress(&p, g_kvt); uint8_t* kvt = (uint8_t*)p;

    gn_kernel<<<BATCH * N_GROUPS, 256>>>(x, gnw, gnb, xn);

    gemm128<<<dim3(L_DIM / 128, (3 * C_DIM) / 128, BATCH), 256>>>(
        qkvw, xn, qkvb, nullptr, qkv, 3 * C_DIM, C_DIM, L_DIM);

    conv_kv<<<dim3(64, BATCH * NHEADS), 256>>>(qkv, kvt);

    cudaFuncSetAttribute(attn_mma,
                         cudaFuncAttributeMaxDynamicSharedMemorySize, SMEM_ATTN);
    attn_mma<<<dim3(L_DIM / 128, BATCH * NHEADS), 256, SMEM_ATTN>>>(qkv, kvt, att);

    gemm128<<<dim3(L_DIM / 128, C_DIM / 128, BATCH), 256>>>(
        pw, att, pb, x, out, C_DIM, C_DIM, L_DIM);
}